// round 4
// baseline (speedup 1.0000x reference)
#include <cuda_runtime.h>
#include <cstdint>

#define K_CODES 1024
#define D       256
#define BM      64
#define BN      128
#define DK      64
#define PITCH_X 260   // floats; 65 16B-quads per row (odd) -> conflict-free LDS.128
#define PITCH_E 68    // floats; 17 16B-quads per row (odd) -> conflict-free LDS.128
#define NCHUNK  32    // 8 code-tiles * 4 dk chunks

__device__ float  g_Se[K_CODES];
__device__ double g_partial[1024];

// packed f32x2 fma: acc.lo += a.lo*b.lo ; acc.hi += a.hi*b.hi
#define FMA2(acc, a, b) \
    asm("fma.rn.f32x2 %0, %1, %2, %0;" : "+l"(acc) : "l"(a), "l"(b))

#define CP_ASYNC16(dst, src) \
    asm volatile("cp.async.cg.shared.global [%0], [%1], 16;\n" :: "r"(dst), "l"(src))
#define CP_COMMIT  asm volatile("cp.async.commit_group;\n" ::)
#define CP_WAIT(n) asm volatile("cp.async.wait_group %0;\n" :: "n"(n))

__global__ void se_kernel(const float* __restrict__ cb) {
    int k = blockIdx.x * blockDim.x + threadIdx.x;
    if (k < K_CODES) {
        const float4* r = (const float4*)(cb + k * D);
        float s = 0.f;
        #pragma unroll 64
        for (int i = 0; i < D / 4; i++) {   // same sequential add order as R1 (bit-exact)
            float4 v = r[i];
            s += v.x * v.x; s += v.y * v.y; s += v.z * v.z; s += v.w * v.w;
        }
        g_Se[k] = s;
    }
}

extern __shared__ __align__(16) float smem[];

__global__ __launch_bounds__(256, 1)
void vq_kernel(const float* __restrict__ x, const float* __restrict__ cb,
               float* __restrict__ out_q, float* __restrict__ out_idx) {
    float* xs  = smem;                          // BM * PITCH_X      = 16640 f
    float* es0 = xs + BM * PITCH_X;             // BN * PITCH_E      =  8704 f
    float* es1 = es0 + BN * PITCH_E;            // BN * PITCH_E      =  8704 f
    float* Ses = es1 + BN * PITCH_E;            // K_CODES           =  1024 f
    float* Sxs = Ses + K_CODES;                 // BM
    int*   idxs = (int*)(Sxs + BM);             // BM
    // reduction scratch reuses es0 region (after main loop)
    float*  redv = es0;                         // BM*16 floats
    int*    redi = (int*)(es0 + BM * 16);       // BM*16 ints
    double* redd = (double*)es0;                // 256 doubles

    const int tid = threadIdx.x;
    const int tx  = tid & 15;
    const int ty  = tid >> 4;
    const int row0 = blockIdx.x * BM;

    // ---- async load: x tile + first codebook chunk; Se table via LDG ----
    {
        const float* src = x + (size_t)row0 * D;
        #pragma unroll
        for (int u = 0; u < 16; u++) {          // 64 rows * 64 quads = 4096 / 256
            int f = u * 256 + tid;
            int r = f >> 6, d4 = f & 63;
            unsigned dst = (unsigned)__cvta_generic_to_shared(xs + r * PITCH_X + d4 * 4);
            CP_ASYNC16(dst, src + r * D + d4 * 4);
        }
        CP_COMMIT;                              // group: xs
        #pragma unroll
        for (int u = 0; u < 8; u++) {           // chunk 0 -> es0 (128 codes x 64 d)
            int f = u * 256 + tid;
            int c = f >> 4, d4 = f & 15;
            unsigned dst = (unsigned)__cvta_generic_to_shared(es0 + c * PITCH_E + d4 * 4);
            CP_ASYNC16(dst, cb + c * D + d4 * 4);
        }
        CP_COMMIT;                              // group: chunk0
        for (int u = tid; u < K_CODES; u += 256) Ses[u] = g_Se[u];
    }
    CP_WAIT(1);                                 // xs arrived (chunk0 may still fly)
    __syncthreads();

    // ---- per-row Sx = sum(x^2), same sequential order as reference-matched R1 ----
    if (tid < BM) {
        const float4* r = (const float4*)(xs + tid * PITCH_X);
        float s = 0.f;
        #pragma unroll 4
        for (int i = 0; i < 64; i++) {
            float4 v = r[i];
            s += v.x * v.x; s += v.y * v.y; s += v.z * v.z; s += v.w * v.w;
        }
        Sxs[tid] = s;
    }
    __syncthreads();

    float sx[4];
    #pragma unroll
    for (int i = 0; i < 4; i++) sx[i] = Sxs[ty * 4 + i];

    float minv[4];
    int   mini[4];
    #pragma unroll
    for (int i = 0; i < 4; i++) { minv[i] = 3.4e38f; mini[i] = 0; }

    unsigned long long acc[4][8];
    #pragma unroll
    for (int i = 0; i < 4; i++)
        #pragma unroll
        for (int j = 0; j < 8; j++) acc[i][j] = 0ull;

    // ---- main loop: 32 chunks (8 code-tiles x 4 dk), double-buffered ----
    for (int ch = 0; ch < NCHUNK; ch++) {
        float* ebuf = (ch & 1) ? es1 : es0;
        __syncthreads();                        // buf[(ch+1)&1] consumers (iter ch-1) done
        if (ch + 1 < NCHUNK) {
            int ct1 = (ch + 1) >> 2, dk1 = (ch + 1) & 3;
            float* enext = ((ch + 1) & 1) ? es1 : es0;
            const float* src = cb + (size_t)(ct1 * BN) * D + dk1 * DK;
            #pragma unroll
            for (int u = 0; u < 8; u++) {
                int f = u * 256 + tid;
                int c = f >> 4, d4 = f & 15;
                unsigned dst = (unsigned)__cvta_generic_to_shared(enext + c * PITCH_E + d4 * 4);
                CP_ASYNC16(dst, src + c * D + d4 * 4);
            }
            CP_COMMIT;
            CP_WAIT(1);                         // chunk ch complete
        } else {
            CP_WAIT(0);
        }
        __syncthreads();

        const float* abase = xs + (ty * 4) * PITCH_X + (ch & 3) * DK;
        const float* bbase = ebuf + tx * PITCH_E;
        #pragma unroll 1
        for (int d4 = 0; d4 < 16; d4++) {
            ulonglong2 A[4], B[8];
            #pragma unroll
            for (int i = 0; i < 4; i++)
                A[i] = *(const ulonglong2*)(abase + i * PITCH_X + d4 * 4);
            #pragma unroll
            for (int j = 0; j < 8; j++)
                B[j] = *(const ulonglong2*)(bbase + j * 16 * PITCH_E + d4 * 4);
            #pragma unroll
            for (int i = 0; i < 4; i++)
                #pragma unroll
                for (int j = 0; j < 8; j++) {
                    FMA2(acc[i][j], A[i].x, B[j].x);
                    FMA2(acc[i][j], A[i].y, B[j].y);
                }
        }

        if ((ch & 3) == 3) {
            // epilogue for code-tile ct: d = (Sx + Se) - 2*dot on the fp32 grid
            int ct = ch >> 2;
            #pragma unroll
            for (int j = 0; j < 8; j++) {
                int code = ct * BN + j * 16 + tx;
                float se = Ses[code];
                #pragma unroll
                for (int i = 0; i < 4; i++) {
                    unsigned long long a = acc[i][j];
                    float lo = __uint_as_float((unsigned)(a & 0xffffffffull));
                    float hi = __uint_as_float((unsigned)(a >> 32));
                    float dot = lo + hi;
                    float val = (sx[i] + se) - 2.0f * dot;
                    if (val < minv[i]) { minv[i] = val; mini[i] = code; }
                    acc[i][j] = 0ull;
                }
            }
        }
    }

    __syncthreads();  // es buffers free -> reuse for reductions
    #pragma unroll
    for (int i = 0; i < 4; i++) {
        redv[(ty * 4 + i) * 16 + tx] = minv[i];
        redi[(ty * 4 + i) * 16 + tx] = mini[i];
    }
    __syncthreads();

    if (tid < BM) {
        float bv = redv[tid * 16];
        int   bi = redi[tid * 16];
        for (int t = 1; t < 16; t++) {
            float v = redv[tid * 16 + t];
            int   c = redi[tid * 16 + t];
            if (v < bv || (v == bv && c < bi)) { bv = v; bi = c; }
        }
        idxs[tid] = bi;
        out_idx[row0 + tid] = (float)bi;
    }
    __syncthreads();

    // ---- quantized output (x + (q - x), fp32 like reference STE) + loss ----
    double lacc = 0.0;
    #pragma unroll 4
    for (int u = 0; u < 16; u++) {              // 64 rows * 64 quads = 4096 / 256
        int f = u * 256 + tid;
        int r = f >> 6, d4 = f & 63;
        float4 q  = *(const float4*)(cb + (size_t)idxs[r] * D + d4 * 4);
        float4 xv = *(const float4*)(xs + r * PITCH_X + d4 * 4);
        float dx = q.x - xv.x, dy = q.y - xv.y, dz = q.z - xv.z, dw = q.w - xv.w;
        float4 o = make_float4(xv.x + dx, xv.y + dy, xv.z + dz, xv.w + dw);
        *(float4*)(out_q + (size_t)(row0 + r) * D + d4 * 4) = o;
        float s0 = dx * dx, s1 = dy * dy, s2 = dz * dz, s3 = dw * dw;
        lacc += (double)s0 + (double)s1 + (double)s2 + (double)s3;
    }
    __syncthreads();            // done reading redv/redi region
    redd[tid] = lacc;
    __syncthreads();
    for (int s = 128; s > 0; s >>= 1) {   // fixed-order -> deterministic
        if (tid < s) redd[tid] += redd[tid + s];
        __syncthreads();
    }
    if (tid == 0) g_partial[blockIdx.x] = redd[0];
}

__global__ void finish_kernel(float* __restrict__ out_loss, int nblocks, double inv_nd) {
    if (threadIdx.x == 0 && blockIdx.x == 0) {
        double s = 0.0;
        for (int i = 0; i < nblocks; i++) s += g_partial[i];
        *out_loss = (float)(s * inv_nd);
    }
}

extern "C" void kernel_launch(void* const* d_in, const int* in_sizes, int n_in,
                              void* d_out, int out_size) {
    const float* x  = (const float*)d_in[0];
    const float* cb = (const float*)d_in[1];
    float* out = (float*)d_out;

    const int nelem = in_sizes[0];      // 16*2048*256 = 8388608
    const int N     = nelem / D;        // 32768
    const int nblocks = N / BM;         // 512

    float* out_q    = out;
    float* out_idx  = out + nelem;
    float* out_loss = out + nelem + N;

    const int smem_bytes = (BM * PITCH_X + 2 * BN * PITCH_E + K_CODES + BM) * 4 + BM * 4;
    cudaFuncSetAttribute(vq_kernel, cudaFuncAttributeMaxDynamicSharedMemorySize, smem_bytes);

    se_kernel<<<(K_CODES + 127) / 128, 128>>>(cb);
    vq_kernel<<<nblocks, 256, smem_bytes>>>(x, cb, out_q, out_idx);
    finish_kernel<<<1, 32>>>(out_loss, nblocks, 1.0 / (double)nelem);
}

// round 6
// speedup vs baseline: 1.7977x; 1.7977x over previous
#include <cuda_runtime.h>
#include <cstdint>

#define K_CODES 1024
#define D       256
#define BM      64
#define BN      128
#define DK      64
#define PITCH_X 260   // floats; 65 16B-quads/row (odd) -> conflict-free LDS.128
#define PITCH_E 68    // floats; 17 16B-quads/row (odd) -> conflict-free octets

__device__ float  g_Se[K_CODES];
__device__ double g_partial[1024];

// packed f32x2 fma: acc.lo += a.lo*b.lo ; acc.hi += a.hi*b.hi
#define FMA2(acc, a, b) \
    asm("fma.rn.f32x2 %0, %1, %2, %0;" : "+l"(acc) : "l"(a), "l"(b))

__global__ void se_kernel(const float* __restrict__ cb) {
    int k = blockIdx.x * blockDim.x + threadIdx.x;
    if (k < K_CODES) {
        const float4* r = (const float4*)(cb + k * D);
        float s = 0.f;
        #pragma unroll 4
        for (int i = 0; i < D / 4; i++) {
            float4 v = r[i];
            s += v.x * v.x; s += v.y * v.y; s += v.z * v.z; s += v.w * v.w;
        }
        g_Se[k] = s;
    }
}

extern __shared__ __align__(16) float smem[];

__global__ __launch_bounds__(256, 2)
void vq_kernel(const float* __restrict__ x, const float* __restrict__ cb,
               float* __restrict__ out_q, float* __restrict__ out_idx) {
    float* xs  = smem;                          // BM * PITCH_X = 16640 f
    float* es  = xs + BM * PITCH_X;             // BN * PITCH_E =  8704 f
    float* Ses = es + BN * PITCH_E;             // 1024 f
    float* Sxs = Ses + K_CODES;                 // 64 f
    int*   idxs = (int*)(Sxs + BM);             // 64 i
    // post-loop reduction scratch reuses es region
    float*  redv = es;                          // 64*32 floats
    int*    redi = (int*)(es + BM * 32);        // 64*32 ints
    double* redd = (double*)es;                 // 256 doubles

    const int tid = threadIdx.x;
    const int tx  = tid & 31;                   // code lane within warp
    const int wy  = tid >> 5;                   // warp id -> row group (8 rows)
    const int row0 = blockIdx.x * BM;

    // ---- load x tile (full D resident) + Se table ----
    {
        const float4* src = (const float4*)(x + (size_t)row0 * D);
        #pragma unroll 4
        for (int u = 0; u < 16; u++) {          // 64 rows * 64 quads / 256 thr
            int f = u * 256 + tid;
            int r = f >> 6, d4 = f & 63;
            float4 v = src[r * 64 + d4];
            *(float4*)(xs + r * PITCH_X + d4 * 4) = v;
        }
        for (int u = tid; u < K_CODES; u += 256) Ses[u] = g_Se[u];
    }
    __syncthreads();

    // ---- per-row Sx = sum(x^2), same sequential order as R1 (bit-exact) ----
    if (tid < BM) {
        const float4* r = (const float4*)(xs + tid * PITCH_X);
        float s = 0.f;
        #pragma unroll 4
        for (int i = 0; i < 64; i++) {
            float4 v = r[i];
            s += v.x * v.x; s += v.y * v.y; s += v.z * v.z; s += v.w * v.w;
        }
        Sxs[tid] = s;
    }
    __syncthreads();

    float sx[8];
    #pragma unroll
    for (int i = 0; i < 8; i++) sx[i] = Sxs[wy * 8 + i];

    float minv[8];
    int   mini[8];
    #pragma unroll
    for (int i = 0; i < 8; i++) { minv[i] = 3.4e38f; mini[i] = 0; }

    unsigned long long acc[8][4];
    #pragma unroll
    for (int i = 0; i < 8; i++)
        #pragma unroll
        for (int j = 0; j < 4; j++) acc[i][j] = 0ull;

    // ---- main loop: 8 code-tiles x 4 dk chunks, synchronous loads (R1 style) ----
    for (int ct = 0; ct < K_CODES / BN; ct++) {
        for (int dk = 0; dk < D / DK; dk++) {
            __syncthreads();                    // previous consumers of es done
            // load codebook chunk: 128 codes x 64 d
            const float* src = cb + (size_t)(ct * BN) * D + dk * DK;
            #pragma unroll
            for (int u = 0; u < 8; u++) {
                int f = u * 256 + tid;          // [0, 2048)
                int c = f >> 4, d4 = f & 15;
                float4 v = *(const float4*)(src + c * D + d4 * 4);
                *(float4*)(es + c * PITCH_E + d4 * 4) = v;
            }
            __syncthreads();

            const float* abase = xs + (wy * 8) * PITCH_X + dk * DK;
            const float* bbase = es + tx * PITCH_E;
            #pragma unroll 1
            for (int d4 = 0; d4 < 16; d4++) {
                ulonglong2 B[4];
                #pragma unroll
                for (int j = 0; j < 4; j++)     // codes j*32 + tx
                    B[j] = *(const ulonglong2*)(bbase + j * 32 * PITCH_E + d4 * 4);
                // rows in two halves of 4 -> lower live-register pressure
                ulonglong2 A[4];
                #pragma unroll
                for (int i = 0; i < 4; i++)
                    A[i] = *(const ulonglong2*)(abase + i * PITCH_X + d4 * 4);
                #pragma unroll
                for (int i = 0; i < 4; i++)
                    #pragma unroll
                    for (int j = 0; j < 4; j++) {
                        FMA2(acc[i][j], A[i].x, B[j].x);
                        FMA2(acc[i][j], A[i].y, B[j].y);
                    }
                #pragma unroll
                for (int i = 0; i < 4; i++)
                    A[i] = *(const ulonglong2*)(abase + (i + 4) * PITCH_X + d4 * 4);
                #pragma unroll
                for (int i = 0; i < 4; i++)
                    #pragma unroll
                    for (int j = 0; j < 4; j++) {
                        FMA2(acc[i + 4][j], A[i].x, B[j].x);
                        FMA2(acc[i + 4][j], A[i].y, B[j].y);
                    }
            }
        }

        // epilogue for code-tile ct: d = (Sx + Se) - 2*dot on the fp32 grid
        #pragma unroll
        for (int j = 0; j < 4; j++) {
            int code = ct * BN + j * 32 + tx;
            float se = Ses[code];
            #pragma unroll
            for (int i = 0; i < 8; i++) {
                unsigned long long a = acc[i][j];
                float lo = __uint_as_float((unsigned)(a & 0xffffffffull));
                float hi = __uint_as_float((unsigned)(a >> 32));
                float dot = lo + hi;
                float val = (sx[i] + se) - 2.0f * dot;
                if (val < minv[i]) { minv[i] = val; mini[i] = code; }
                acc[i][j] = 0ull;
            }
        }
    }

    __syncthreads();  // es free -> reuse for reductions
    #pragma unroll
    for (int i = 0; i < 8; i++) {
        redv[(wy * 8 + i) * 32 + tx] = minv[i];
        redi[(wy * 8 + i) * 32 + tx] = mini[i];
    }
    __syncthreads();

    if (tid < BM) {
        float bv = redv[tid * 32];
        int   bi = redi[tid * 32];
        for (int t = 1; t < 32; t++) {
            float v = redv[tid * 32 + t];
            int   c = redi[tid * 32 + t];
            if (v < bv || (v == bv && c < bi)) { bv = v; bi = c; }
        }
        idxs[tid] = bi;
        out_idx[row0 + tid] = (float)bi;
    }
    __syncthreads();

    // ---- quantized output (x + (q - x), fp32 like reference STE) + loss ----
    double lacc = 0.0;
    #pragma unroll 4
    for (int u = 0; u < 16; u++) {              // 64 rows * 64 quads / 256 thr
        int f = u * 256 + tid;
        int r = f >> 6, d4 = f & 63;
        float4 q  = *(const float4*)(cb + (size_t)idxs[r] * D + d4 * 4);
        float4 xv = *(const float4*)(xs + r * PITCH_X + d4 * 4);
        float dx = q.x - xv.x, dy = q.y - xv.y, dz = q.z - xv.z, dw = q.w - xv.w;
        float4 o = make_float4(xv.x + dx, xv.y + dy, xv.z + dz, xv.w + dw);
        *(float4*)(out_q + (size_t)(row0 + r) * D + d4 * 4) = o;
        float s0 = dx * dx, s1 = dy * dy, s2 = dz * dz, s3 = dw * dw;
        lacc += (double)s0 + (double)s1 + (double)s2 + (double)s3;
    }
    __syncthreads();            // done reading redv/redi region
    redd[tid] = lacc;
    __syncthreads();
    for (int s = 128; s > 0; s >>= 1) {   // fixed-order -> deterministic
        if (tid < s) redd[tid] += redd[tid + s];
        __syncthreads();
    }
    if (tid == 0) g_partial[blockIdx.x] = redd[0];
}

__global__ void finish_kernel(float* __restrict__ out_loss, int nblocks, double inv_nd) {
    if (threadIdx.x == 0 && blockIdx.x == 0) {
        double s = 0.0;
        for (int i = 0; i < nblocks; i++) s += g_partial[i];
        *out_loss = (float)(s * inv_nd);
    }
}

extern "C" void kernel_launch(void* const* d_in, const int* in_sizes, int n_in,
                              void* d_out, int out_size) {
    const float* x  = (const float*)d_in[0];
    const float* cb = (const float*)d_in[1];
    float* out = (float*)d_out;

    const int nelem = in_sizes[0];      // 16*2048*256 = 8388608
    const int N     = nelem / D;        // 32768
    const int nblocks = N / BM;         // 512

    float* out_q    = out;
    float* out_idx  = out + nelem;
    float* out_loss = out + nelem + N;

    const int smem_bytes = (BM * PITCH_X + BN * PITCH_E + K_CODES + BM) * 4 + BM * 4;
    cudaFuncSetAttribute(vq_kernel, cudaFuncAttributeMaxDynamicSharedMemorySize, smem_bytes);

    se_kernel<<<(K_CODES + 127) / 128, 128>>>(cb);
    vq_kernel<<<nblocks, 256, smem_bytes>>>(x, cb, out_q, out_idx);
    finish_kernel<<<1, 32>>>(out_loss, nblocks, 1.0 / (double)nelem);
}